// round 3
// baseline (speedup 1.0000x reference)
#include <cuda_runtime.h>
#include <math.h>

// ---------------- problem constants ----------------
#define EDIM   128      // embed size E
#define HDIM   256      // hidden size H
#define QDIM   256      // query size Q
#define BATCH  256
#define N_ENT  200000
#define N_REL  500
#define N_NODES 100000
#define N_NEW  50000
#define NEDGE  200000

// ---------------- device scratch (no runtime allocation allowed) ----------------
__device__ float g_nodeWs  [(size_t)N_NODES * HDIM];   // node_hidden @ Ws
__device__ float g_entCand [(size_t)N_ENT  * HDIM];    // entity_emb @ cand_W[0:128]
__device__ float g_relWr   [N_REL * HDIM];             // relation_emb @ Wr
__device__ float g_relWqr  [N_REL * HDIM];             // relation_emb @ Wqr
__device__ float g_relCand [N_REL * HDIM];             // relation_emb @ cand_W[128:256]
__device__ float g_agg     [(size_t)N_NEW * 2 * EDIM]; // segment sum of messages
__device__ float g_hprev   [(size_t)N_NEW * HDIM];
__device__ float g_hnew    [(size_t)N_NEW * HDIM];
__device__ float g_hnewCand[(size_t)N_NEW * HDIM];     // h_new @ cand_W[256:512]
__device__ float g_gx      [(size_t)N_NEW * 3 * HDIM];
__device__ float g_gh      [(size_t)N_NEW * 3 * HDIM];
__device__ float g_WihT    [2 * EDIM * 3 * HDIM];      // [256][768]
__device__ float g_WhhT    [HDIM * 3 * HDIM];          // [256][768]
__device__ float g_qdot    [BATCH];

// ---------------- utility kernels ----------------
__global__ void zero_kernel(float4* __restrict__ p, int n4) {
    int i = blockIdx.x * blockDim.x + threadIdx.x;
    if (i < n4) p[i] = make_float4(0.f, 0.f, 0.f, 0.f);
}

// out[c][r] = in[r][c], in is R x C (both multiples of 32)
__global__ void transpose_kernel(const float* __restrict__ in, float* __restrict__ out,
                                 int R, int C) {
    __shared__ float t[32][33];
    int c0 = blockIdx.x * 32, r0 = blockIdx.y * 32;
    int x = threadIdx.x, y = threadIdx.y;      // 32 x 8
    #pragma unroll
    for (int i = 0; i < 32; i += 8)
        t[y + i][x] = in[(long)(r0 + y + i) * C + (c0 + x)];
    __syncthreads();
    #pragma unroll
    for (int i = 0; i < 32; i += 8)
        out[(long)(c0 + y + i) * R + (r0 + x)] = t[x][y + i];
}

// ---------------- tiled fp32 GEMM ----------------
// C[M,N] = act(A[M,K] @ B[K,N] + bias), optional row-gather on A.
// N multiple of 128, K multiple of 16. ACT: 0 = none, 1 = leaky_relu(0.01)
#define BM 128
#define BN 128
#define BK 16
template<int ACT>
__global__ __launch_bounds__(256)
void sgemm_kernel(const float* __restrict__ A, const float* __restrict__ B,
                  float* __restrict__ C, const float* __restrict__ bias,
                  const int* __restrict__ gidx, int M, int N, int K)
{
    __shared__ __align__(16) float As[BK][BM];
    __shared__ __align__(16) float Bs[BK][BN];

    int tid = threadIdx.x;
    int rowBase = blockIdx.y * BM;
    int colBase = blockIdx.x * BN;
    int tx = tid & 15, ty = tid >> 4;

    // A load mapping: row = tid/2 (0..127), col8 = (tid&1)*8
    int aRowL = tid >> 1;
    int aColL = (tid & 1) * 8;
    int aRowG = rowBase + aRowL;
    bool aValid = aRowG < M;
    long aRowIdx = 0;
    if (aValid) aRowIdx = gidx ? (long)gidx[aRowG] : (long)aRowG;
    const float* aBase = A + aRowIdx * K + aColL;

    // B load mapping: row = tid/16 (0..15), col = (tid&15)*8
    int bRowL = tid >> 4;
    int bColL = (tid & 15) * 8;
    const float* bBase = B + (long)bRowL * N + colBase + bColL;

    float acc[8][8];
    #pragma unroll
    for (int i = 0; i < 8; i++)
        #pragma unroll
        for (int j = 0; j < 8; j++) acc[i][j] = 0.f;

    for (int kk = 0; kk < K; kk += BK) {
        float4 a0 = make_float4(0,0,0,0), a1 = a0;
        if (aValid) {
            a0 = *(const float4*)(aBase + kk);
            a1 = *(const float4*)(aBase + kk + 4);
        }
        As[aColL + 0][aRowL] = a0.x; As[aColL + 1][aRowL] = a0.y;
        As[aColL + 2][aRowL] = a0.z; As[aColL + 3][aRowL] = a0.w;
        As[aColL + 4][aRowL] = a1.x; As[aColL + 5][aRowL] = a1.y;
        As[aColL + 6][aRowL] = a1.z; As[aColL + 7][aRowL] = a1.w;

        const float* bp = bBase + (long)kk * N;
        *(float4*)&Bs[bRowL][bColL]     = *(const float4*)bp;
        *(float4*)&Bs[bRowL][bColL + 4] = *(const float4*)(bp + 4);
        __syncthreads();

        #pragma unroll
        for (int k = 0; k < BK; k++) {
            float4 af0 = *(const float4*)&As[k][ty * 8];
            float4 af1 = *(const float4*)&As[k][ty * 8 + 4];
            float4 bf0 = *(const float4*)&Bs[k][tx * 8];
            float4 bf1 = *(const float4*)&Bs[k][tx * 8 + 4];
            float ar[8] = {af0.x, af0.y, af0.z, af0.w, af1.x, af1.y, af1.z, af1.w};
            float br[8] = {bf0.x, bf0.y, bf0.z, bf0.w, bf1.x, bf1.y, bf1.z, bf1.w};
            #pragma unroll
            for (int i = 0; i < 8; i++)
                #pragma unroll
                for (int j = 0; j < 8; j++)
                    acc[i][j] = fmaf(ar[i], br[j], acc[i][j]);
        }
        __syncthreads();
    }

    // epilogue
    int col0 = colBase + tx * 8;
    float bv[8];
    #pragma unroll
    for (int j = 0; j < 8; j++) bv[j] = bias ? bias[col0 + j] : 0.f;

    #pragma unroll
    for (int i = 0; i < 8; i++) {
        int r = rowBase + ty * 8 + i;
        if (r >= M) continue;
        float v[8];
        #pragma unroll
        for (int j = 0; j < 8; j++) {
            float x = acc[i][j] + bv[j];
            if (ACT == 1) x = (x > 0.f) ? x : 0.01f * x;
            v[j] = x;
        }
        float* cp = C + (long)r * N + col0;
        *(float4*)cp       = make_float4(v[0], v[1], v[2], v[3]);
        *(float4*)(cp + 4) = make_float4(v[4], v[5], v[6], v[7]);
    }
}

// ---------------- per-edge attention + message scatter ----------------
// one warp per edge
__global__ void edge_attn_kernel(const float* __restrict__ rel_emb,
                                 const float* __restrict__ ent_emb,
                                 const float* __restrict__ bqr,
                                 const float* __restrict__ w_alpha,
                                 const float* __restrict__ b_alpha,
                                 const int* __restrict__ head_node,
                                 const int* __restrict__ edge_rel,
                                 const int* __restrict__ query_rel,
                                 const int* __restrict__ tail_ent,
                                 const int* __restrict__ tail_node)
{
    int w = (blockIdx.x * blockDim.x + threadIdx.x) >> 5;
    int lane = threadIdx.x & 31;
    if (w >= NEDGE) return;
    int hn = head_node[w], er = edge_rel[w], qr = query_rel[w];

    const float4* nr = (const float4*)(g_nodeWs + (long)hn * HDIM);
    const float4* rr = (const float4*)(g_relWr  + er * HDIM);
    const float4* qp = (const float4*)(g_relWqr + qr * HDIM);
    const float4* bq = (const float4*)bqr;
    const float4* wa = (const float4*)w_alpha;

    float acc = 0.f;
    #pragma unroll
    for (int i = 0; i < 2; i++) {
        int c = lane + i * 32;
        float4 a = nr[c], b = rr[c], q = qp[c], d = bq[c], wv = wa[c];
        float f;
        f = a.x + b.x + q.x + d.x; f = fmaxf(f, 0.f); acc = fmaf(f, wv.x, acc);
        f = a.y + b.y + q.y + d.y; f = fmaxf(f, 0.f); acc = fmaf(f, wv.y, acc);
        f = a.z + b.z + q.z + d.z; f = fmaxf(f, 0.f); acc = fmaf(f, wv.z, acc);
        f = a.w + b.w + q.w + d.w; f = fmaxf(f, 0.f); acc = fmaf(f, wv.w, acc);
    }
    #pragma unroll
    for (int o = 16; o > 0; o >>= 1) acc += __shfl_xor_sync(0xffffffffu, acc, o);
    float alpha = 1.f / (1.f + expf(-(acc + b_alpha[0])));

    int te = tail_ent[w], tn = tail_node[w];
    float* arow = g_agg + (long)tn * (2 * EDIM);
    const float* hrrow = rel_emb + (long)er * EDIM;
    const float* terow = ent_emb + (long)te * EDIM;
    #pragma unroll
    for (int i = 0; i < 4; i++) {
        int c = lane + i * 32;
        atomicAdd(&arow[c], alpha * hrrow[c]);
    }
    #pragma unroll
    for (int i = 0; i < 4; i++) {
        int c = lane + i * 32;
        atomicAdd(&arow[EDIM + c], alpha * terow[c]);
    }
}

// ---------------- GRU gate combine + LayerNorm ----------------
// one block (256 threads) per new node row
__global__ void gru_ln_kernel(const float* __restrict__ ln_g, const float* __restrict__ ln_b)
{
    int i = blockIdx.x;
    int j = threadIdx.x;
    const float* gxr = g_gx + (long)i * (3 * HDIM);
    const float* ghr = g_gh + (long)i * (3 * HDIM);
    float xr = gxr[j], xz = gxr[HDIM + j], xn = gxr[2 * HDIM + j];
    float hr = ghr[j], hz = ghr[HDIM + j], hn = ghr[2 * HDIM + j];
    float r = 1.f / (1.f + expf(-(xr + hr)));
    float z = 1.f / (1.f + expf(-(xz + hz)));
    float n = tanhf(xn + r * hn);
    float hp = g_hprev[(long)i * HDIM + j];
    float h = (1.f - z) * n + z * hp;

    // block reduction for mean / var
    __shared__ float s1[8], s2[8];
    float v1 = h, v2 = h * h;
    #pragma unroll
    for (int o = 16; o > 0; o >>= 1) {
        v1 += __shfl_xor_sync(0xffffffffu, v1, o);
        v2 += __shfl_xor_sync(0xffffffffu, v2, o);
    }
    int warp = j >> 5, lane = j & 31;
    if (lane == 0) { s1[warp] = v1; s2[warp] = v2; }
    __syncthreads();
    float sum = 0.f, sq = 0.f;
    #pragma unroll
    for (int k = 0; k < 8; k++) { sum += s1[k]; sq += s2[k]; }
    float mean = sum * (1.f / HDIM);
    float var = sq * (1.f / HDIM) - mean * mean;
    float inv = rsqrtf(var + 1e-5f);
    g_hnew[(long)i * HDIM + j] = (h - mean) * inv * ln_g[j] + ln_b[j];
}

// ---------------- qdot[b] = query_repr[b] . rank_W[256:512] ----------------
__global__ void qdot_kernel(const float* __restrict__ qrep, const float* __restrict__ rank_W)
{
    int w = (blockIdx.x * blockDim.x + threadIdx.x) >> 5;
    int lane = threadIdx.x & 31;
    if (w >= BATCH) return;
    const float4* q  = (const float4*)(qrep + (long)w * QDIM);
    const float4* rw = (const float4*)(rank_W + HDIM);
    float acc = 0.f;
    #pragma unroll
    for (int i = 0; i < 2; i++) {
        int c = lane + i * 32;
        float4 a = q[c], b = rw[c];
        acc = fmaf(a.x, b.x, acc); acc = fmaf(a.y, b.y, acc);
        acc = fmaf(a.z, b.z, acc); acc = fmaf(a.w, b.w, acc);
    }
    #pragma unroll
    for (int o = 16; o > 0; o >>= 1) acc += __shfl_xor_sync(0xffffffffu, acc, o);
    if (lane == 0) g_qdot[w] = acc;
}

// ---------------- final per-edge scoring ----------------
__global__ void score_kernel(const float* __restrict__ cand_b,
                             const float* __restrict__ rank_W,
                             const float* __restrict__ rank_b,
                             const int* __restrict__ tail_ent,
                             const int* __restrict__ edge_rel,
                             const int* __restrict__ tail_node,
                             const int* __restrict__ batch_idx,
                             float* __restrict__ out)
{
    int w = (blockIdx.x * blockDim.x + threadIdx.x) >> 5;
    int lane = threadIdx.x & 31;
    if (w >= NEDGE) return;
    int te = tail_ent[w], er = edge_rel[w], tn = tail_node[w], bi = batch_idx[w];
    const float4* ec = (const float4*)(g_entCand  + (long)te * HDIM);
    const float4* rc = (const float4*)(g_relCand  + er * HDIM);
    const float4* hc = (const float4*)(g_hnewCand + (long)tn * HDIM);
    const float4* cb = (const float4*)cand_b;
    const float4* rw = (const float4*)rank_W;
    float acc = 0.f;
    #pragma unroll
    for (int i = 0; i < 2; i++) {
        int c = lane + i * 32;
        float4 a = ec[c], b = rc[c], h = hc[c], bb = cb[c], wv = rw[c];
        float v;
        v = a.x + b.x + h.x + bb.x; v = (v > 0.f) ? v : 0.01f * v; acc = fmaf(v, wv.x, acc);
        v = a.y + b.y + h.y + bb.y; v = (v > 0.f) ? v : 0.01f * v; acc = fmaf(v, wv.y, acc);
        v = a.z + b.z + h.z + bb.z; v = (v > 0.f) ? v : 0.01f * v; acc = fmaf(v, wv.z, acc);
        v = a.w + b.w + h.w + bb.w; v = (v > 0.f) ? v : 0.01f * v; acc = fmaf(v, wv.w, acc);
    }
    #pragma unroll
    for (int o = 16; o > 0; o >>= 1) acc += __shfl_xor_sync(0xffffffffu, acc, o);
    if (lane == 0) out[w] = acc + g_qdot[bi] + rank_b[0];
}

// ---------------- launch ----------------
extern "C" void kernel_launch(void* const* d_in, const int* in_sizes, int n_in,
                              void* d_out, int out_size)
{
    const float* ent      = (const float*)d_in[0];
    const float* rel      = (const float*)d_in[1];
    const float* nodeh    = (const float*)d_in[2];
    const float* qrep     = (const float*)d_in[3];
    const float* Ws       = (const float*)d_in[4];
    const float* Wr       = (const float*)d_in[5];
    const float* Wqr      = (const float*)d_in[6];
    const float* bqr      = (const float*)d_in[7];
    const float* w_alpha  = (const float*)d_in[8];
    const float* b_alpha  = (const float*)d_in[9];
    const float* W_ih     = (const float*)d_in[10];
    const float* W_hh     = (const float*)d_in[11];
    const float* b_ih     = (const float*)d_in[12];
    const float* b_hh     = (const float*)d_in[13];
    const float* We2h_W   = (const float*)d_in[14];
    const float* We2h_b   = (const float*)d_in[15];
    const float* cand_W   = (const float*)d_in[16];
    const float* cand_b   = (const float*)d_in[17];
    const float* rank_W   = (const float*)d_in[18];
    const float* rank_b   = (const float*)d_in[19];
    const float* ln_g     = (const float*)d_in[20];
    const float* ln_b     = (const float*)d_in[21];
    const int* head_node     = (const int*)d_in[22];
    const int* edge_rel      = (const int*)d_in[23];
    const int* tail_ent      = (const int*)d_in[24];
    const int* tail_node     = (const int*)d_in[25];
    const int* query_rel     = (const int*)d_in[26];
    const int* batch_idx     = (const int*)d_in[27];
    const int* tail_node_ent = (const int*)d_in[28];
    float* out = (float*)d_out;

    void* pv;
    float *p_nodeWs, *p_entCand, *p_relWr, *p_relWqr, *p_relCand;
    float *p_agg, *p_hprev, *p_hnew, *p_hnewCand, *p_gx, *p_gh, *p_WihT, *p_WhhT;
    cudaGetSymbolAddress(&pv, g_nodeWs);   p_nodeWs   = (float*)pv;
    cudaGetSymbolAddress(&pv, g_entCand);  p_entCand  = (float*)pv;
    cudaGetSymbolAddress(&pv, g_relWr);    p_relWr    = (float*)pv;
    cudaGetSymbolAddress(&pv, g_relWqr);   p_relWqr   = (float*)pv;
    cudaGetSymbolAddress(&pv, g_relCand);  p_relCand  = (float*)pv;
    cudaGetSymbolAddress(&pv, g_agg);      p_agg      = (float*)pv;
    cudaGetSymbolAddress(&pv, g_hprev);    p_hprev    = (float*)pv;
    cudaGetSymbolAddress(&pv, g_hnew);     p_hnew     = (float*)pv;
    cudaGetSymbolAddress(&pv, g_hnewCand); p_hnewCand = (float*)pv;
    cudaGetSymbolAddress(&pv, g_gx);       p_gx       = (float*)pv;
    cudaGetSymbolAddress(&pv, g_gh);       p_gh       = (float*)pv;
    cudaGetSymbolAddress(&pv, g_WihT);     p_WihT     = (float*)pv;
    cudaGetSymbolAddress(&pv, g_WhhT);     p_WhhT     = (float*)pv;

    // 1. zero the aggregation buffer
    {
        int n4 = N_NEW * 2 * EDIM / 4;                  // 3.2M float4
        zero_kernel<<<(n4 + 255) / 256, 256>>>((float4*)p_agg, n4);
    }
    // 2. transpose GRU weights to [K, N] layout
    transpose_kernel<<<dim3(256 / 32, 768 / 32), dim3(32, 8)>>>(W_ih, p_WihT, 768, 256);
    transpose_kernel<<<dim3(256 / 32, 768 / 32), dim3(32, 8)>>>(W_hh, p_WhhT, 768, 256);

    // 3. relation-table precomputes (tiny)
    sgemm_kernel<0><<<dim3(2, 4), 256>>>(rel, Wr,  p_relWr,  nullptr, nullptr, N_REL, HDIM, EDIM);
    sgemm_kernel<0><<<dim3(2, 4), 256>>>(rel, Wqr, p_relWqr, nullptr, nullptr, N_REL, HDIM, EDIM);
    sgemm_kernel<0><<<dim3(2, 4), 256>>>(rel, cand_W + 128 * 256, p_relCand, nullptr, nullptr, N_REL, HDIM, EDIM);

    // 4. nodeWs = node_hidden @ Ws
    sgemm_kernel<0><<<dim3(2, (N_NODES + 127) / 128), 256>>>(nodeh, Ws, p_nodeWs, nullptr, nullptr, N_NODES, HDIM, HDIM);
    // 5. entCand = entity_emb @ cand_W[0:128]
    sgemm_kernel<0><<<dim3(2, (N_ENT + 127) / 128), 256>>>(ent, cand_W, p_entCand, nullptr, nullptr, N_ENT, HDIM, EDIM);
    // 6. h_prev = lrelu(entity_emb[tail_node_ent] @ We2h + b)
    sgemm_kernel<1><<<dim3(2, (N_NEW + 127) / 128), 256>>>(ent, We2h_W, p_hprev, We2h_b, tail_node_ent, N_NEW, HDIM, EDIM);
    // 7. query dot partial
    qdot_kernel<<<BATCH / 8, 256>>>(qrep, rank_W);

    // 8. per-edge attention + scatter
    edge_attn_kernel<<<NEDGE / 8, 256>>>(rel, ent, bqr, w_alpha, b_alpha,
                                         head_node, edge_rel, query_rel, tail_ent, tail_node);

    // 9/10. GRU gate GEMMs
    sgemm_kernel<0><<<dim3(6, (N_NEW + 127) / 128), 256>>>(p_agg,   p_WihT, p_gx, b_ih, nullptr, N_NEW, 3 * HDIM, 2 * EDIM);
    sgemm_kernel<0><<<dim3(6, (N_NEW + 127) / 128), 256>>>(p_hprev, p_WhhT, p_gh, b_hh, nullptr, N_NEW, 3 * HDIM, HDIM);

    // 11. GRU combine + LayerNorm
    gru_ln_kernel<<<N_NEW, 256>>>(ln_g, ln_b);

    // 12. hnewCand = h_new @ cand_W[256:512]
    sgemm_kernel<0><<<dim3(2, (N_NEW + 127) / 128), 256>>>(p_hnew, cand_W + 256 * 256, p_hnewCand, nullptr, nullptr, N_NEW, HDIM, HDIM);

    // 13. final per-edge scores
    score_kernel<<<NEDGE / 8, 256>>>(cand_b, rank_W, rank_b,
                                     tail_ent, edge_rel, tail_node, batch_idx, out);
}

// round 6
// speedup vs baseline: 1.6208x; 1.6208x over previous
#include <cuda_runtime.h>
#include <cuda_bf16.h>
#include <math.h>
#include <stdint.h>

// ---------------- problem constants ----------------
#define EDIM   128
#define HDIM   256
#define QDIM   256
#define BATCH  256
#define N_ENT  200000
#define N_REL  500
#define N_NODES 100000
#define N_NEW  50000
#define NEDGE  200000

// ---------------- device scratch ----------------
__device__ float g_nodeWs  [(size_t)N_NODES * HDIM];
__device__ float g_entCand [(size_t)N_ENT  * HDIM];
__device__ float g_relWr   [N_REL * HDIM];
__device__ float g_relWqr  [N_REL * HDIM];
__device__ float g_relCand [N_REL * HDIM];
__device__ float g_agg     [(size_t)N_NEW * 2 * EDIM];
__device__ float g_hprev   [(size_t)N_NEW * HDIM];
__device__ float g_hnew    [(size_t)N_NEW * HDIM];
__device__ float g_hnewCand[(size_t)N_NEW * HDIM];
__device__ float g_gx      [(size_t)N_NEW * 3 * HDIM];
__device__ float g_gh      [(size_t)N_NEW * 3 * HDIM];
__device__ float g_qdot    [BATCH];

// bf16 hi/lo weight copies, [N, K] with K contiguous
__device__ __align__(16) __nv_bfloat16 g_bWs_h  [256 * 256], g_bWs_l  [256 * 256];
__device__ __align__(16) __nv_bfloat16 g_bWr_h  [256 * 128], g_bWr_l  [256 * 128];
__device__ __align__(16) __nv_bfloat16 g_bWqr_h [256 * 128], g_bWqr_l [256 * 128];
__device__ __align__(16) __nv_bfloat16 g_bCa_h  [256 * 128], g_bCa_l  [256 * 128];
__device__ __align__(16) __nv_bfloat16 g_bCb_h  [256 * 128], g_bCb_l  [256 * 128];
__device__ __align__(16) __nv_bfloat16 g_bCc_h  [256 * 256], g_bCc_l  [256 * 256];
__device__ __align__(16) __nv_bfloat16 g_bWe2h_h[256 * 128], g_bWe2h_l[256 * 128];
__device__ __align__(16) __nv_bfloat16 g_bWih_h [768 * 256], g_bWih_l [768 * 256];
__device__ __align__(16) __nv_bfloat16 g_bWhh_h [768 * 256], g_bWhh_l [768 * 256];

// ---------------- small utility kernels ----------------
__global__ void zero_kernel(float4* __restrict__ p, int n4) {
    int i = blockIdx.x * blockDim.x + threadIdx.x;
    if (i < n4) p[i] = make_float4(0.f, 0.f, 0.f, 0.f);
}

// W[K,N] row-major -> hi/lo bf16 [N,K]
__global__ void convT_kernel(const float* __restrict__ W, __nv_bfloat16* __restrict__ H,
                             __nv_bfloat16* __restrict__ L, int K, int N) {
    int idx = blockIdx.x * blockDim.x + threadIdx.x;
    if (idx >= N * K) return;
    int n = idx / K, k = idx - n * K;
    float x = W[(size_t)k * N + n];
    __nv_bfloat16 h = __float2bfloat16_rn(x);
    H[idx] = h;
    L[idx] = __float2bfloat16_rn(x - __bfloat162float(h));
}

// W already [N,K] -> hi/lo bf16
__global__ void convD_kernel(const float* __restrict__ W, __nv_bfloat16* __restrict__ H,
                             __nv_bfloat16* __restrict__ L, int total) {
    int idx = blockIdx.x * blockDim.x + threadIdx.x;
    if (idx >= total) return;
    float x = W[idx];
    __nv_bfloat16 h = __float2bfloat16_rn(x);
    H[idx] = h;
    L[idx] = __float2bfloat16_rn(x - __bfloat162float(h));
}

// ---------------- mma.sync bf16-split GEMM ----------------
// C[M, Nt] tile (128 x 128) = act(A[M,K] @ B^T + bias)
// B is [Ntotal, K] bf16 hi/lo (K contiguous == .col fragment layout).
// K multiple of 32, Nt multiple of 128. Optional row gather on A.

__device__ __forceinline__ void mma16816(float* c, const uint32_t* a, const uint32_t* b) {
    asm volatile("mma.sync.aligned.m16n8k16.row.col.f32.bf16.bf16.f32 "
        "{%0,%1,%2,%3}, {%4,%5,%6,%7}, {%8,%9}, {%0,%1,%2,%3};"
        : "+f"(c[0]), "+f"(c[1]), "+f"(c[2]), "+f"(c[3])
        : "r"(a[0]), "r"(a[1]), "r"(a[2]), "r"(a[3]), "r"(b[0]), "r"(b[1]));
}

#define STRW 20   // b32 stride per 32-element (bf16) row: 16 data + 4 pad (bank-conflict-free)

template<int ACT>
__global__ __launch_bounds__(256)
void mma_gemm(const float* __restrict__ A,
              const __nv_bfloat16* __restrict__ Bh, const __nv_bfloat16* __restrict__ Bl,
              float* __restrict__ C, const float* __restrict__ bias,
              const int* __restrict__ gidx, int M, int Nt, int K)
{
    __shared__ uint32_t sAh[128 * STRW], sAl[128 * STRW];
    __shared__ uint32_t sBh[128 * STRW], sBl[128 * STRW];

    int tid = threadIdx.x;
    int lane = tid & 31, wid = tid >> 5;
    int wm = wid & 3, wn = wid >> 2;           // warp tile: rows wm*32, cols wn*64
    int g = lane >> 2, tc = lane & 3;
    int rowBase = blockIdx.y * 128, colBase = blockIdx.x * 128;

    // A global load mapping: row = tid/2, half q = tid&1 (16 floats each)
    int arow = tid >> 1;
    int aq = tid & 1;
    int r = rowBase + arow;
    bool aValid = r < M;
    long ridx = 0;
    if (aValid) ridx = gidx ? (long)gidx[r] : (long)r;
    const float* aPtr = A + ridx * (long)K + aq * 16;

    // B global load mapping: n-row = tid/2, half q (16 bf16 each)
    const __nv_bfloat16* bhPtr = Bh + (size_t)(colBase + arow) * K + aq * 16;
    const __nv_bfloat16* blPtr = Bl + (size_t)(colBase + arow) * K + aq * 16;

    float acc[2][8][4];
    #pragma unroll
    for (int im = 0; im < 2; im++)
        #pragma unroll
        for (int in_ = 0; in_ < 8; in_++)
            #pragma unroll
            for (int q = 0; q < 4; q++) acc[im][in_][q] = 0.f;

    for (int kk = 0; kk < K; kk += 32) {
        // ---- A tile: fp32 -> bf16 hi/lo split into smem ----
        #pragma unroll
        for (int i = 0; i < 4; i++) {
            float4 v = make_float4(0.f, 0.f, 0.f, 0.f);
            if (aValid) v = *(const float4*)(aPtr + kk + i * 4);
            float xs[4] = {v.x, v.y, v.z, v.w};
            float hx[4], lx[4];
            #pragma unroll
            for (int j = 0; j < 4; j++) {
                __nv_bfloat16 h = __float2bfloat16_rn(xs[j]);
                float hf = __bfloat162float(h);
                hx[j] = hf; lx[j] = xs[j] - hf;
            }
            uint32_t h01, h23, l01, l23;
            asm("cvt.rn.bf16x2.f32 %0, %1, %2;" : "=r"(h01) : "f"(hx[1]), "f"(hx[0]));
            asm("cvt.rn.bf16x2.f32 %0, %1, %2;" : "=r"(h23) : "f"(hx[3]), "f"(hx[2]));
            asm("cvt.rn.bf16x2.f32 %0, %1, %2;" : "=r"(l01) : "f"(lx[1]), "f"(lx[0]));
            asm("cvt.rn.bf16x2.f32 %0, %1, %2;" : "=r"(l23) : "f"(lx[3]), "f"(lx[2]));
            int cp = arow * STRW + aq * 8 + i * 2;
            sAh[cp] = h01; sAh[cp + 1] = h23;
            sAl[cp] = l01; sAl[cp + 1] = l23;
        }
        // ---- B tile: bf16 hi/lo copy into smem ----
        #pragma unroll
        for (int i = 0; i < 2; i++) {
            uint4 hv = *(const uint4*)(bhPtr + kk + i * 8);
            uint4 lv = *(const uint4*)(blPtr + kk + i * 8);
            int cp = arow * STRW + aq * 8 + i * 4;
            *(uint4*)&sBh[cp] = hv;
            *(uint4*)&sBl[cp] = lv;
        }
        __syncthreads();

        #pragma unroll
        for (int ko = 0; ko < 16; ko += 8) {   // two k16 steps (b32 col offset 0, 8)
            uint32_t ah[2][4], al[2][4];
            #pragma unroll
            for (int im = 0; im < 2; im++) {
                int r0 = (wm * 32 + im * 16 + g) * STRW + ko + tc;
                int r1 = r0 + 8 * STRW;
                ah[im][0] = sAh[r0]; ah[im][1] = sAh[r1];
                ah[im][2] = sAh[r0 + 4]; ah[im][3] = sAh[r1 + 4];
                al[im][0] = sAl[r0]; al[im][1] = sAl[r1];
                al[im][2] = sAl[r0 + 4]; al[im][3] = sAl[r1 + 4];
            }
            uint32_t bb[8][2];
            #pragma unroll
            for (int in_ = 0; in_ < 8; in_++) {
                int b0 = (wn * 64 + in_ * 8 + g) * STRW + ko + tc;
                bb[in_][0] = sBh[b0]; bb[in_][1] = sBh[b0 + 4];
            }
            // Ah*Bh + Al*Bh
            #pragma unroll
            for (int im = 0; im < 2; im++)
                #pragma unroll
                for (int in_ = 0; in_ < 8; in_++) {
                    mma16816(acc[im][in_], ah[im], bb[in_]);
                    mma16816(acc[im][in_], al[im], bb[in_]);
                }
            // reload B lo, Ah*Bl
            #pragma unroll
            for (int in_ = 0; in_ < 8; in_++) {
                int b0 = (wn * 64 + in_ * 8 + g) * STRW + ko + tc;
                bb[in_][0] = sBl[b0]; bb[in_][1] = sBl[b0 + 4];
            }
            #pragma unroll
            for (int im = 0; im < 2; im++)
                #pragma unroll
                for (int in_ = 0; in_ < 8; in_++)
                    mma16816(acc[im][in_], ah[im], bb[in_]);
        }
        __syncthreads();
    }

    // ---- epilogue ----
    #pragma unroll
    for (int im = 0; im < 2; im++) {
        int row0 = rowBase + wm * 32 + im * 16 + g;
        int row1 = row0 + 8;
        #pragma unroll
        for (int in_ = 0; in_ < 8; in_++) {
            int col = colBase + wn * 64 + in_ * 8 + tc * 2;
            float b0 = bias ? bias[col] : 0.f;
            float b1 = bias ? bias[col + 1] : 0.f;
            float v0 = acc[im][in_][0] + b0, v1 = acc[im][in_][1] + b1;
            float v2 = acc[im][in_][2] + b0, v3 = acc[im][in_][3] + b1;
            if (ACT == 1) {
                v0 = (v0 > 0.f) ? v0 : 0.01f * v0;
                v1 = (v1 > 0.f) ? v1 : 0.01f * v1;
                v2 = (v2 > 0.f) ? v2 : 0.01f * v2;
                v3 = (v3 > 0.f) ? v3 : 0.01f * v3;
            }
            if (row0 < M) *(float2*)(C + (size_t)row0 * Nt + col) = make_float2(v0, v1);
            if (row1 < M) *(float2*)(C + (size_t)row1 * Nt + col) = make_float2(v2, v3);
        }
    }
}

// ---------------- per-edge attention + message scatter ----------------
__global__ void edge_attn_kernel(const float* __restrict__ rel_emb,
                                 const float* __restrict__ ent_emb,
                                 const float* __restrict__ bqr,
                                 const float* __restrict__ w_alpha,
                                 const float* __restrict__ b_alpha,
                                 const int* __restrict__ head_node,
                                 const int* __restrict__ edge_rel,
                                 const int* __restrict__ query_rel,
                                 const int* __restrict__ tail_ent,
                                 const int* __restrict__ tail_node)
{
    int w = (blockIdx.x * blockDim.x + threadIdx.x) >> 5;
    int lane = threadIdx.x & 31;
    if (w >= NEDGE) return;
    int hn = head_node[w], er = edge_rel[w], qr = query_rel[w];

    const float4* nr = (const float4*)(g_nodeWs + (long)hn * HDIM);
    const float4* rr = (const float4*)(g_relWr  + er * HDIM);
    const float4* qp = (const float4*)(g_relWqr + qr * HDIM);
    const float4* bq = (const float4*)bqr;
    const float4* wa = (const float4*)w_alpha;

    float acc = 0.f;
    #pragma unroll
    for (int i = 0; i < 2; i++) {
        int c = lane + i * 32;
        float4 a = nr[c], b = rr[c], q = qp[c], d = bq[c], wv = wa[c];
        float f;
        f = a.x + b.x + q.x + d.x; f = fmaxf(f, 0.f); acc = fmaf(f, wv.x, acc);
        f = a.y + b.y + q.y + d.y; f = fmaxf(f, 0.f); acc = fmaf(f, wv.y, acc);
        f = a.z + b.z + q.z + d.z; f = fmaxf(f, 0.f); acc = fmaf(f, wv.z, acc);
        f = a.w + b.w + q.w + d.w; f = fmaxf(f, 0.f); acc = fmaf(f, wv.w, acc);
    }
    #pragma unroll
    for (int o = 16; o > 0; o >>= 1) acc += __shfl_xor_sync(0xffffffffu, acc, o);
    float alpha = 1.f / (1.f + expf(-(acc + b_alpha[0])));

    int te = tail_ent[w], tn = tail_node[w];
    float* arow = g_agg + (long)tn * (2 * EDIM);
    const float* hrrow = rel_emb + (long)er * EDIM;
    const float* terow = ent_emb + (long)te * EDIM;
    #pragma unroll
    for (int i = 0; i < 4; i++) {
        int c = lane + i * 32;
        atomicAdd(&arow[c], alpha * hrrow[c]);
    }
    #pragma unroll
    for (int i = 0; i < 4; i++) {
        int c = lane + i * 32;
        atomicAdd(&arow[EDIM + c], alpha * terow[c]);
    }
}

// ---------------- GRU gate combine + LayerNorm ----------------
__global__ void gru_ln_kernel(const float* __restrict__ ln_g, const float* __restrict__ ln_b)
{
    int i = blockIdx.x;
    int j = threadIdx.x;
    const float* gxr = g_gx + (long)i * (3 * HDIM);
    const float* ghr = g_gh + (long)i * (3 * HDIM);
    float xr = gxr[j], xz = gxr[HDIM + j], xn = gxr[2 * HDIM + j];
    float hr = ghr[j], hz = ghr[HDIM + j], hn = ghr[2 * HDIM + j];
    float r = 1.f / (1.f + expf(-(xr + hr)));
    float z = 1.f / (1.f + expf(-(xz + hz)));
    float n = tanhf(xn + r * hn);
    float hp = g_hprev[(long)i * HDIM + j];
    float h = (1.f - z) * n + z * hp;

    __shared__ float s1[8], s2[8];
    float v1 = h, v2 = h * h;
    #pragma unroll
    for (int o = 16; o > 0; o >>= 1) {
        v1 += __shfl_xor_sync(0xffffffffu, v1, o);
        v2 += __shfl_xor_sync(0xffffffffu, v2, o);
    }
    int warp = j >> 5, lane = j & 31;
    if (lane == 0) { s1[warp] = v1; s2[warp] = v2; }
    __syncthreads();
    float sum = 0.f, sq = 0.f;
    #pragma unroll
    for (int k = 0; k < 8; k++) { sum += s1[k]; sq += s2[k]; }
    float mean = sum * (1.f / HDIM);
    float var = sq * (1.f / HDIM) - mean * mean;
    float inv = rsqrtf(var + 1e-5f);
    g_hnew[(long)i * HDIM + j] = (h - mean) * inv * ln_g[j] + ln_b[j];
}

// ---------------- qdot[b] = query_repr[b] . rank_W[256:512] ----------------
__global__ void qdot_kernel(const float* __restrict__ qrep, const float* __restrict__ rank_W)
{
    int w = (blockIdx.x * blockDim.x + threadIdx.x) >> 5;
    int lane = threadIdx.x & 31;
    if (w >= BATCH) return;
    const float4* q  = (const float4*)(qrep + (long)w * QDIM);
    const float4* rw = (const float4*)(rank_W + HDIM);
    float acc = 0.f;
    #pragma unroll
    for (int i = 0; i < 2; i++) {
        int c = lane + i * 32;
        float4 a = q[c], b = rw[c];
        acc = fmaf(a.x, b.x, acc); acc = fmaf(a.y, b.y, acc);
        acc = fmaf(a.z, b.z, acc); acc = fmaf(a.w, b.w, acc);
    }
    #pragma unroll
    for (int o = 16; o > 0; o >>= 1) acc += __shfl_xor_sync(0xffffffffu, acc, o);
    if (lane == 0) g_qdot[w] = acc;
}

// ---------------- final per-edge scoring ----------------
__global__ void score_kernel(const float* __restrict__ cand_b,
                             const float* __restrict__ rank_W,
                             const float* __restrict__ rank_b,
                             const int* __restrict__ tail_ent,
                             const int* __restrict__ edge_rel,
                             const int* __restrict__ tail_node,
                             const int* __restrict__ batch_idx,
                             float* __restrict__ out)
{
    int w = (blockIdx.x * blockDim.x + threadIdx.x) >> 5;
    int lane = threadIdx.x & 31;
    if (w >= NEDGE) return;
    int te = tail_ent[w], er = edge_rel[w], tn = tail_node[w], bi = batch_idx[w];
    const float4* ec = (const float4*)(g_entCand  + (long)te * HDIM);
    const float4* rc = (const float4*)(g_relCand  + er * HDIM);
    const float4* hc = (const float4*)(g_hnewCand + (long)tn * HDIM);
    const float4* cb = (const float4*)cand_b;
    const float4* rw = (const float4*)rank_W;
    float acc = 0.f;
    #pragma unroll
    for (int i = 0; i < 2; i++) {
        int c = lane + i * 32;
        float4 a = ec[c], b = rc[c], h = hc[c], bb = cb[c], wv = rw[c];
        float v;
        v = a.x + b.x + h.x + bb.x; v = (v > 0.f) ? v : 0.01f * v; acc = fmaf(v, wv.x, acc);
        v = a.y + b.y + h.y + bb.y; v = (v > 0.f) ? v : 0.01f * v; acc = fmaf(v, wv.y, acc);
        v = a.z + b.z + h.z + bb.z; v = (v > 0.f) ? v : 0.01f * v; acc = fmaf(v, wv.z, acc);
        v = a.w + b.w + h.w + bb.w; v = (v > 0.f) ? v : 0.01f * v; acc = fmaf(v, wv.w, acc);
    }
    #pragma unroll
    for (int o = 16; o > 0; o >>= 1) acc += __shfl_xor_sync(0xffffffffu, acc, o);
    if (lane == 0) out[w] = acc + g_qdot[bi] + rank_b[0];
}

// ---------------- launch ----------------
extern "C" void kernel_launch(void* const* d_in, const int* in_sizes, int n_in,
                              void* d_out, int out_size)
{
    const float* ent      = (const float*)d_in[0];
    const float* rel      = (const float*)d_in[1];
    const float* nodeh    = (const float*)d_in[2];
    const float* qrep     = (const float*)d_in[3];
    const float* Ws       = (const float*)d_in[4];
    const float* Wr       = (const float*)d_in[5];
    const float* Wqr      = (const float*)d_in[6];
    const float* bqr      = (const float*)d_in[7];
    const float* w_alpha  = (const float*)d_in[8];
    const float* b_alpha  = (const float*)d_in[9];
    const float* W_ih     = (const float*)d_in[10];
    const float* W_hh     = (const float*)d_in[11];
    const float* b_ih     = (const float*)d_in[12];
    const float* b_hh     = (const float*)d_in[13];
    const float* We2h_W   = (const float*)d_in[14];
    const float* We2h_b   = (const float*)d_in[15];
    const float* cand_W   = (const float*)d_in[16];
    const float* cand_b   = (const float*)d_in[17];
    const float* rank_W   = (const float*)d_in[18];
    const float* rank_b   = (const float*)d_in[19];
    const float* ln_g     = (const float*)d_in[20];
    const float* ln_b     = (const float*)d_in[21];
    const int* head_node     = (const int*)d_in[22];
    const int* edge_rel      = (const int*)d_in[23];
    const int* tail_ent      = (const int*)d_in[24];
    const int* tail_node     = (const int*)d_in[25];
    const int* query_rel     = (const int*)d_in[26];
    const int* batch_idx     = (const int*)d_in[27];
    const int* tail_node_ent = (const int*)d_in[28];
    float* out = (float*)d_out;

    void* pv;
    float *p_agg, *p_hprev, *p_hnew, *p_gx, *p_gh;
    float *p_nodeWs, *p_entCand, *p_relWr, *p_relWqr, *p_relCand, *p_hnewCand;
    cudaGetSymbolAddress(&pv, g_agg);      p_agg      = (float*)pv;
    cudaGetSymbolAddress(&pv, g_hprev);    p_hprev    = (float*)pv;
    cudaGetSymbolAddress(&pv, g_hnew);     p_hnew     = (float*)pv;
    cudaGetSymbolAddress(&pv, g_gx);       p_gx       = (float*)pv;
    cudaGetSymbolAddress(&pv, g_gh);       p_gh       = (float*)pv;
    cudaGetSymbolAddress(&pv, g_nodeWs);   p_nodeWs   = (float*)pv;
    cudaGetSymbolAddress(&pv, g_entCand);  p_entCand  = (float*)pv;
    cudaGetSymbolAddress(&pv, g_relWr);    p_relWr    = (float*)pv;
    cudaGetSymbolAddress(&pv, g_relWqr);   p_relWqr   = (float*)pv;
    cudaGetSymbolAddress(&pv, g_relCand);  p_relCand  = (float*)pv;
    cudaGetSymbolAddress(&pv, g_hnewCand); p_hnewCand = (float*)pv;

    __nv_bfloat16 *bWs_h, *bWs_l, *bWr_h, *bWr_l, *bWqr_h, *bWqr_l;
    __nv_bfloat16 *bCa_h, *bCa_l, *bCb_h, *bCb_l, *bCc_h, *bCc_l;
    __nv_bfloat16 *bWe2h_h, *bWe2h_l, *bWih_h, *bWih_l, *bWhh_h, *bWhh_l;
    cudaGetSymbolAddress(&pv, g_bWs_h);   bWs_h   = (__nv_bfloat16*)pv;
    cudaGetSymbolAddress(&pv, g_bWs_l);   bWs_l   = (__nv_bfloat16*)pv;
    cudaGetSymbolAddress(&pv, g_bWr_h);   bWr_h   = (__nv_bfloat16*)pv;
    cudaGetSymbolAddress(&pv, g_bWr_l);   bWr_l   = (__nv_bfloat16*)pv;
    cudaGetSymbolAddress(&pv, g_bWqr_h);  bWqr_h  = (__nv_bfloat16*)pv;
    cudaGetSymbolAddress(&pv, g_bWqr_l);  bWqr_l  = (__nv_bfloat16*)pv;
    cudaGetSymbolAddress(&pv, g_bCa_h);   bCa_h   = (__nv_bfloat16*)pv;
    cudaGetSymbolAddress(&pv, g_bCa_l);   bCa_l   = (__nv_bfloat16*)pv;
    cudaGetSymbolAddress(&pv, g_bCb_h);   bCb_h   = (__nv_bfloat16*)pv;
    cudaGetSymbolAddress(&pv, g_bCb_l);   bCb_l   = (__nv_bfloat16*)pv;
    cudaGetSymbolAddress(&pv, g_bCc_h);   bCc_h   = (__nv_bfloat16*)pv;
    cudaGetSymbolAddress(&pv, g_bCc_l);   bCc_l   = (__nv_bfloat16*)pv;
    cudaGetSymbolAddress(&pv, g_bWe2h_h); bWe2h_h = (__nv_bfloat16*)pv;
    cudaGetSymbolAddress(&pv, g_bWe2h_l); bWe2h_l = (__nv_bfloat16*)pv;
    cudaGetSymbolAddress(&pv, g_bWih_h);  bWih_h  = (__nv_bfloat16*)pv;
    cudaGetSymbolAddress(&pv, g_bWih_l);  bWih_l  = (__nv_bfloat16*)pv;
    cudaGetSymbolAddress(&pv, g_bWhh_h);  bWhh_h  = (__nv_bfloat16*)pv;
    cudaGetSymbolAddress(&pv, g_bWhh_l);  bWhh_l  = (__nv_bfloat16*)pv;

    // 1. zero aggregation buffer
    {
        int n4 = N_NEW * 2 * EDIM / 4;
        zero_kernel<<<(n4 + 255) / 256, 256>>>((float4*)p_agg, n4);
    }
    // 2. weight conversion to bf16 hi/lo [N, K]
    convT_kernel<<<(256 * 256 + 255) / 256, 256>>>(Ws,  bWs_h,  bWs_l,  256, 256);
    convT_kernel<<<(256 * 128 + 255) / 256, 256>>>(Wr,  bWr_h,  bWr_l,  128, 256);
    convT_kernel<<<(256 * 128 + 255) / 256, 256>>>(Wqr, bWqr_h, bWqr_l, 128, 256);
    convT_kernel<<<(256 * 128 + 255) / 256, 256>>>(cand_W,             bCa_h, bCa_l, 128, 256);
    convT_kernel<<<(256 * 128 + 255) / 256, 256>>>(cand_W + 128 * 256, bCb_h, bCb_l, 128, 256);
    convT_kernel<<<(256 * 256 + 255) / 256, 256>>>(cand_W + 256 * 256, bCc_h, bCc_l, 256, 256);
    convT_kernel<<<(256 * 128 + 255) / 256, 256>>>(We2h_W, bWe2h_h, bWe2h_l, 128, 256);
    convD_kernel<<<(768 * 256 + 255) / 256, 256>>>(W_ih, bWih_h, bWih_l, 768 * 256);
    convD_kernel<<<(768 * 256 + 255) / 256, 256>>>(W_hh, bWhh_h, bWhh_l, 768 * 256);

    // 3. relation-table precomputes (tiny GEMMs)
    mma_gemm<0><<<dim3(2, 4), 256>>>(rel, bWr_h,  bWr_l,  p_relWr,   nullptr, nullptr, N_REL, 256, 128);
    mma_gemm<0><<<dim3(2, 4), 256>>>(rel, bWqr_h, bWqr_l, p_relWqr,  nullptr, nullptr, N_REL, 256, 128);
    mma_gemm<0><<<dim3(2, 4), 256>>>(rel, bCb_h,  bCb_l,  p_relCand, nullptr, nullptr, N_REL, 256, 128);

    // 4. nodeWs = node_hidden @ Ws
    mma_gemm<0><<<dim3(2, (N_NODES + 127) / 128), 256>>>(
        nodeh, bWs_h, bWs_l, p_nodeWs, nullptr, nullptr, N_NODES, 256, 256);
    // 5. entCand = entity_emb @ cand_W[0:128]
    mma_gemm<0><<<dim3(2, (N_ENT + 127) / 128), 256>>>(
        ent, bCa_h, bCa_l, p_entCand, nullptr, nullptr, N_ENT, 256, 128);
    // 6. h_prev = lrelu(entity_emb[tail_node_ent] @ We2h + b)
    mma_gemm<1><<<dim3(2, (N_NEW + 127) / 128), 256>>>(
        ent, bWe2h_h, bWe2h_l, p_hprev, We2h_b, tail_node_ent, N_NEW, 256, 128);
    // 7. query dot partial
    qdot_kernel<<<BATCH / 8, 256>>>(qrep, rank_W);

    // 8. per-edge attention + scatter
    edge_attn_kernel<<<NEDGE / 8, 256>>>(rel, ent, bqr, w_alpha, b_alpha,
                                         head_node, edge_rel, query_rel, tail_ent, tail_node);

    // 9/10. GRU gate GEMMs (N = 768)
    mma_gemm<0><<<dim3(6, (N_NEW + 127) / 128), 256>>>(
        p_agg, bWih_h, bWih_l, p_gx, b_ih, nullptr, N_NEW, 768, 256);
    mma_gemm<0><<<dim3(6, (N_NEW + 127) / 128), 256>>>(
        p_hprev, bWhh_h, bWhh_l, p_gh, b_hh, nullptr, N_NEW, 768, 256);

    // 11. GRU combine + LayerNorm
    gru_ln_kernel<<<N_NEW, 256>>>(ln_g, ln_b);

    // 12. hnewCand = h_new @ cand_W[256:512]
    mma_gemm<0><<<dim3(2, (N_NEW + 127) / 128), 256>>>(
        p_hnew, bCc_h, bCc_l, p_hnewCand, nullptr, nullptr, N_NEW, 256, 256);

    // 13. final per-edge scores
    score_kernel<<<NEDGE / 8, 256>>>(cand_b, rank_W, rank_b,
                                     tail_ent, edge_rel, tail_node, batch_idx, out);
}